// round 3
// baseline (speedup 1.0000x reference)
#include <cuda_runtime.h>
#include <cuda_bf16.h>
#include <math.h>
#include <cstdint>

#define BATCH 128
#define NPT   500
#define NROWS (BATCH*NPT)

typedef unsigned long long ull;

// ---------------- scratch ----------------
__device__ __align__(256) float g_bufA[65536000];
__device__ __align__(256) float g_bufB[65536000];
__device__ __align__(256) int   g_idx1[BATCH * 500];
__device__ __align__(256) int   g_idx2[BATCH * 1000];
__device__ __align__(256) float g_w3p[256 * 264];
__device__ __align__(256) float g_w5p[384 * 392];

// ---------------- small helpers ----------------
__device__ __forceinline__ uint32_t smem_u32(const void* p) {
    uint32_t a;
    asm("{ .reg .u64 t; cvta.to.shared.u64 t, %1; cvt.u32.u64 %0, t; }" : "=r"(a) : "l"(p));
    return a;
}
__device__ __forceinline__ void sts64(uint32_t addr, ull v) {
    asm volatile("st.shared.b64 [%0], %1;" :: "r"(addr), "l"(v) : "memory");
}
__device__ __forceinline__ void ldm_x4(uint32_t* r, uint32_t addr) {
    asm volatile("ldmatrix.sync.aligned.m8n8.x4.shared.b16 {%0,%1,%2,%3}, [%4];"
        : "=r"(r[0]), "=r"(r[1]), "=r"(r[2]), "=r"(r[3]) : "r"(addr));
}
__device__ __forceinline__ void ldm_x2(uint32_t& r0, uint32_t& r1, uint32_t addr) {
    asm volatile("ldmatrix.sync.aligned.m8n8.x2.shared.b16 {%0,%1}, [%2];"
        : "=r"(r0), "=r"(r1) : "r"(addr));
}
__device__ __forceinline__ void mma_bf16(float* d, const uint32_t* a, uint32_t b0, uint32_t b1) {
    asm volatile("mma.sync.aligned.m16n8k16.row.col.f32.bf16.bf16.f32 "
        "{%0,%1,%2,%3}, {%4,%5,%6,%7}, {%8,%9}, {%0,%1,%2,%3};"
        : "+f"(d[0]), "+f"(d[1]), "+f"(d[2]), "+f"(d[3])
        : "r"(a[0]), "r"(a[1]), "r"(a[2]), "r"(a[3]), "r"(b0), "r"(b1));
}
// fp32x4 -> bf16 hi pair-words + bf16 lo (residual) pair-words
__device__ __forceinline__ void cvt_hl(float4 v, uint32_t& h01, uint32_t& h23,
                                       uint32_t& l01, uint32_t& l23) {
    asm("cvt.rn.bf16x2.f32 %0, %1, %2;" : "=r"(h01) : "f"(v.y), "f"(v.x));
    asm("cvt.rn.bf16x2.f32 %0, %1, %2;" : "=r"(h23) : "f"(v.w), "f"(v.z));
    float xh = __uint_as_float(h01 << 16);
    float yh = __uint_as_float(h01 & 0xFFFF0000u);
    float zh = __uint_as_float(h23 << 16);
    float wh = __uint_as_float(h23 & 0xFFFF0000u);
    float rx = v.x - xh, ry = v.y - yh, rz = v.z - zh, rw = v.w - wh;
    asm("cvt.rn.bf16x2.f32 %0, %1, %2;" : "=r"(l01) : "f"(ry), "f"(rx));
    asm("cvt.rn.bf16x2.f32 %0, %1, %2;" : "=r"(l23) : "f"(rw), "f"(rz));
}

// ---------------- HMMA bf16 3-term split GEMM ----------------
// C[m,n] = relu?( sum_k A[m,k]*W[n,k] + bias[n] ).  M%128==0, K%8==0.
// CTA tile 128(M) x 256(N) x 64(K), 8 warps (2M x 4N), warp tile 64x64.
// smem per stage: Ah 16K | Al 16K | Bh 32K | Bl 32K = 96K; double buffered = 192K.
#define G_STAGE 98304
static const int GEMM_SMEM = 2 * G_STAGE;

__device__ __forceinline__ void fill_stage(
    const float* __restrict__ A, const float* __restrict__ W,
    int N, int K, int row0, int col0, int k0, uint32_t base, int tid)
{
#pragma unroll
    for (int i = 0; i < 8; i++) {                  // A: 128 rows x 64 k
        int g = (i << 8) + tid;
        int r = g >> 4, kq = (g & 15) << 2;
        float4 v = make_float4(0.f, 0.f, 0.f, 0.f);
        if (k0 + kq < K) v = *(const float4*)(A + (size_t)(row0 + r) * K + k0 + kq);
        uint32_t h01, h23, l01, l23;
        cvt_hl(v, h01, h23, l01, l23);
        uint32_t off = (uint32_t)(kq << 1);
        uint32_t sw = ((uint32_t)r << 7) + ((((off >> 4) ^ ((uint32_t)r & 7))) << 4) + (off & 8);
        sts64(base + sw,         ((ull)h23 << 32) | h01);
        sts64(base + 16384 + sw, ((ull)l23 << 32) | l01);
    }
#pragma unroll
    for (int i = 0; i < 16; i++) {                 // B: 256 rows x 64 k
        int g = (i << 8) + tid;
        int r = g >> 4, kq = (g & 15) << 2;
        float4 v = make_float4(0.f, 0.f, 0.f, 0.f);
        if ((col0 + r < N) && (k0 + kq < K))
            v = *(const float4*)(W + (size_t)(col0 + r) * K + k0 + kq);
        uint32_t h01, h23, l01, l23;
        cvt_hl(v, h01, h23, l01, l23);
        uint32_t off = (uint32_t)(kq << 1);
        uint32_t sw = ((uint32_t)r << 7) + ((((off >> 4) ^ ((uint32_t)r & 7))) << 4) + (off & 8);
        sts64(base + 32768 + sw, ((ull)h23 << 32) | h01);
        sts64(base + 65536 + sw, ((ull)l23 << 32) | l01);
    }
}

__global__ void __launch_bounds__(256, 1)
gemm_hmma(const float* __restrict__ A, const float* __restrict__ W,
          const float* __restrict__ bias, float* __restrict__ C,
          int M, int N, int K, int relu)
{
    extern __shared__ char smem[];
    uint32_t sb = smem_u32(smem);
    int tid = threadIdx.x, lane = tid & 31, wid = tid >> 5;
    int warp_m = wid & 1;      // 0..1  (64 rows each)
    int warp_n = wid >> 1;     // 0..3  (64 cols each)
    int row0 = blockIdx.y << 7;
    int col0 = blockIdx.x << 8;
    int Nt = N - col0; if (Nt > 256) Nt = 256;
    int n_lim = Nt - warp_n * 64;
    int ni_cnt = (n_lim >= 64) ? 8 : (n_lim > 0 ? (n_lim >> 3) : 0);

    float acc[4][8][4];
#pragma unroll
    for (int a = 0; a < 4; a++)
#pragma unroll
        for (int b = 0; b < 8; b++)
#pragma unroll
            for (int c = 0; c < 4; c++) acc[a][b][c] = 0.f;

    int nst = (K + 63) >> 6;
    fill_stage(A, W, N, K, row0, col0, 0, sb, tid);
    __syncthreads();

    // ldmatrix base addresses (lane-dependent pieces precomputed)
    int a_row = warp_m * 64 + (lane & 15);                 // + mi*16
    int a_chl = lane >> 4;                                 // chunk half
    int b_row = warp_n * 64 + (lane & 7);                  // + ni*8
    int b_chl = (lane >> 3) & 1;

    for (int s = 0; s < nst; s++) {
        uint32_t base = sb + (uint32_t)(s & 1) * G_STAGE;
        if (ni_cnt > 0) {
#pragma unroll
            for (int ks = 0; ks < 4; ks++) {
                uint32_t Ah[4][4], Al[4][4];
#pragma unroll
                for (int mi = 0; mi < 4; mi++) {
                    int rr = a_row + mi * 16;
                    int ch = (ks << 1) + a_chl;
                    uint32_t sw = ((uint32_t)rr << 7) + (((uint32_t)(ch ^ (rr & 7))) << 4);
                    ldm_x4(Ah[mi], base + sw);
                    ldm_x4(Al[mi], base + 16384 + sw);
                }
                if (ni_cnt == 8) {
#pragma unroll
                    for (int ni = 0; ni < 8; ni++) {
                        int nr = b_row + ni * 8;
                        int ch = (ks << 1) + b_chl;
                        uint32_t sw = ((uint32_t)nr << 7) + (((uint32_t)(ch ^ (nr & 7))) << 4);
                        uint32_t bh0, bh1, bl0, bl1;
                        ldm_x2(bh0, bh1, base + 32768 + sw);
                        ldm_x2(bl0, bl1, base + 65536 + sw);
#pragma unroll
                        for (int mi = 0; mi < 4; mi++) {
                            mma_bf16(acc[mi][ni], Ah[mi], bh0, bh1);
                            mma_bf16(acc[mi][ni], Al[mi], bh0, bh1);
                            mma_bf16(acc[mi][ni], Ah[mi], bl0, bl1);
                        }
                    }
                } else {
                    for (int ni = 0; ni < ni_cnt; ni++) {
                        int nr = b_row + ni * 8;
                        int ch = (ks << 1) + b_chl;
                        uint32_t sw = ((uint32_t)nr << 7) + (((uint32_t)(ch ^ (nr & 7))) << 4);
                        uint32_t bh0, bh1, bl0, bl1;
                        ldm_x2(bh0, bh1, base + 32768 + sw);
                        ldm_x2(bl0, bl1, base + 65536 + sw);
#pragma unroll
                        for (int mi = 0; mi < 4; mi++) {
                            mma_bf16(acc[mi][ni], Ah[mi], bh0, bh1);
                            mma_bf16(acc[mi][ni], Al[mi], bh0, bh1);
                            mma_bf16(acc[mi][ni], Ah[mi], bl0, bl1);
                        }
                    }
                }
            }
        }
        if (s + 1 < nst) {
            fill_stage(A, W, N, K, row0, col0, (s + 1) << 6,
                       sb + (uint32_t)((s + 1) & 1) * G_STAGE, tid);
        }
        __syncthreads();
    }

    // epilogue: bias + optional relu, float2 stores
    int er = row0 + warp_m * 64 + (lane >> 2);
    int ec = col0 + warp_n * 64 + ((lane & 3) << 1);
    for (int ni = 0; ni < ni_cnt; ni++) {
        int c = ec + ni * 8;
        float b0 = __ldg(bias + c), b1 = __ldg(bias + c + 1);
#pragma unroll
        for (int mi = 0; mi < 4; mi++) {
            int r = er + mi * 16;
            float2 v0, v1;
            v0.x = acc[mi][ni][0] + b0; v0.y = acc[mi][ni][1] + b1;
            v1.x = acc[mi][ni][2] + b0; v1.y = acc[mi][ni][3] + b1;
            if (relu) {
                v0.x = fmaxf(v0.x, 0.f); v0.y = fmaxf(v0.y, 0.f);
                v1.x = fmaxf(v1.x, 0.f); v1.y = fmaxf(v1.y, 0.f);
            }
            *(float2*)(C + (size_t)r * N + c)       = v0;
            *(float2*)(C + (size_t)(r + 8) * N + c) = v1;
        }
    }
}

// ---------------- weight padding ----------------
__global__ void pack_weights(const float* __restrict__ w3, const float* __restrict__ w5) {
    int t = blockIdx.x * 256 + threadIdx.x;
    const int n3 = 256 * 264;
    if (t < n3) {
        int r = t / 264, c = t - r * 264;
        g_w3p[t] = (c < 259) ? w3[r * 259 + c] : 0.f;
    }
    int t2 = t - n3;
    if (t2 >= 0 && t2 < 384 * 392) {
        int r = t2 / 392, c = t2 - r * 392;
        g_w5p[t2] = (c < 387) ? w5[r * 387 + c] : 0.f;
    }
}

// ---------------- fused conf + concat + first linear ----------------
__global__ void point_mlp1(const float* __restrict__ x,
                           const float* __restrict__ confW, const float* __restrict__ confb,
                           const float* __restrict__ w1, const float* __restrict__ b1) {
    int t = blockIdx.x * 256 + threadIdx.x;
    if (t >= NROWS * 16) return;
    int p = t >> 4, g = t & 15;
    float x0 = x[p * 3], x1 = x[p * 3 + 1], x2 = x[p * 3 + 2];
    float s = confW[0] * x0 + confW[1] * x1 + confW[2] * x2 + confb[0];
    float conf = 1.f / (1.f + expf(-s));
    const float* wr = w1 + (g * 4) * 4;
    float v[4];
#pragma unroll
    for (int r = 0; r < 4; r++) {
        float a = b1[g * 4 + r]
                + wr[r * 4 + 0] * conf + wr[r * 4 + 1] * x0
                + wr[r * 4 + 2] * x1   + wr[r * 4 + 3] * x2;
        v[r] = fmaxf(a, 0.f);
    }
    *(float4*)&g_bufA[(size_t)p * 64 + g * 4] = make_float4(v[0], v[1], v[2], v[3]);
}

// ---------------- farthest point sampling (bitwise-matches XLA) ----------------
__global__ void fps_kernel(const float* __restrict__ x,
                           const int* __restrict__ far1, const int* __restrict__ far2) {
    __shared__ float sxx[512], sxy[512], sxz[512];
    int which = blockIdx.x >> 7;
    int b = blockIdx.x & 127;
    int npoint = which ? 1000 : 500;
    int* out = (which ? g_idx2 : g_idx1) + b * npoint;
    int far = which ? far2[b] : far1[b];
    const float* xb = x + (size_t)b * NPT * 3;
    int lane = threadIdx.x;

    float px[16], py[16], pz[16], dist[16];
#pragma unroll
    for (int j = 0; j < 16; j++) {
        int p = j * 32 + lane;
        if (p < NPT) {
            px[j] = xb[p * 3]; py[j] = xb[p * 3 + 1]; pz[j] = xb[p * 3 + 2];
            dist[j] = 1e10f;
            sxx[p] = px[j]; sxy[p] = py[j]; sxz[p] = pz[j];
        } else {
            px[j] = 0.f; py[j] = 0.f; pz[j] = 0.f;
            dist[j] = -1.0f;   // padding: never selected (valid dists >= 0)
        }
    }
    __syncwarp();

    for (int t = 0; t < npoint; t++) {
        if (lane == 0) out[t] = far;           // emit BEFORE update (matches scan)
        if (t + 1 == npoint) break;
        float cx = sxx[far], cy = sxy[far], cz = sxz[far];
        float nd[16];
#pragma unroll
        for (int j = 0; j < 16; j++) {        // exact unfused ops: match XLA bitwise
            float dx = __fsub_rn(px[j], cx);
            float dy = __fsub_rn(py[j], cy);
            float dz = __fsub_rn(pz[j], cz);
            float d  = __fadd_rn(__fadd_rn(__fmul_rn(dx, dx), __fmul_rn(dy, dy)),
                                 __fmul_rn(dz, dz));
            nd[j] = fminf(dist[j], d);
            dist[j] = nd[j];
        }
        // lane-local max (tree), then warp max on bits (dists >= 0)
        float m[8];
#pragma unroll
        for (int j = 0; j < 8; j++) m[j] = fmaxf(nd[2 * j], nd[2 * j + 1]);
#pragma unroll
        for (int j = 0; j < 4; j++) m[j] = fmaxf(m[j], m[j + 4]);
        m[0] = fmaxf(m[0], m[2]); m[1] = fmaxf(m[1], m[3]);
        float best = fmaxf(m[0], m[1]);
        unsigned mb = __reduce_max_sync(0xffffffffu, __float_as_uint(best));
        // first matching index (smallest point id), tree + warp min
        unsigned c[16];
#pragma unroll
        for (int j = 0; j < 16; j++)
            c[j] = (__float_as_uint(nd[j]) == mb) ? (unsigned)(j * 32 + lane) : 0xffffffffu;
#pragma unroll
        for (int j = 0; j < 8; j++) c[j] = min(c[j], c[j + 8]);
#pragma unroll
        for (int j = 0; j < 4; j++) c[j] = min(c[j], c[j + 4]);
        c[0] = min(c[0], c[2]); c[1] = min(c[1], c[3]);
        far = (int)__reduce_min_sync(0xffffffffu, min(c[0], c[1]));
    }
}

// ---------------- gathers (write zero padding for K alignment) ----------------
__global__ void gather1_kernel(const float* __restrict__ x) {
    int t = blockIdx.x * 256 + threadIdx.x;
    if (t >= NROWS * 66) return;
    int r = t / 66, c4 = t - r * 66;
    int b = r / 500;
    int i = g_idx1[r];
    size_t src = (size_t)b * 500 + i;
    float4 v;
    if (c4 < 64)       v = *(const float4*)&g_bufA[src * 256 + (c4 << 2)];
    else if (c4 == 64) { const float* xp = x + src * 3; v = make_float4(xp[0], xp[1], xp[2], 0.f); }
    else               v = make_float4(0.f, 0.f, 0.f, 0.f);
    *(float4*)&g_bufB[(size_t)r * 264 + (c4 << 2)] = v;
}
__global__ void gather2_kernel(const float* __restrict__ x) {
    int t = blockIdx.x * 256 + threadIdx.x;
    if (t >= 128000 * 98) return;
    int r = t / 98, c4 = t - r * 98;
    int b = r / 1000;
    int i = g_idx2[r];
    size_t src = (size_t)b * 500 + i;
    float4 v;
    if (c4 < 96)       v = *(const float4*)&g_bufA[src * 384 + (c4 << 2)];
    else if (c4 == 96) { const float* xp = x + src * 3; v = make_float4(xp[0], xp[1], xp[2], 0.f); }
    else               v = make_float4(0.f, 0.f, 0.f, 0.f);
    *(float4*)&g_bufB[(size_t)r * 392 + (c4 << 2)] = v;
}

// ---------------- max-pool over the 1000 sampled rows per batch ----------------
__global__ void maxpool_kernel(const float* __restrict__ l8, float* __restrict__ out) {
    int t = blockIdx.x * 256 + threadIdx.x;
    if (t >= BATCH * 512) return;
    int b = t >> 9, c = t & 511;
    const float* p = l8 + (size_t)b * 1000 * 512 + c;
    float m = -1e30f;
#pragma unroll 4
    for (int i = 0; i < 1000; i++) m = fmaxf(m, p[(size_t)i * 512]);
    out[t] = m;
}

// ---------------- launch ----------------
extern "C" void kernel_launch(void* const* d_in, const int* in_sizes, int n_in,
                              void* d_out, int out_size) {
    const float* x     = (const float*)d_in[0];
    const float* confW = (const float*)d_in[1];
    const float* confb = (const float*)d_in[2];
    const float* w1    = (const float*)d_in[3];
    const float* b1    = (const float*)d_in[4];
    const float* w2    = (const float*)d_in[5];
    const float* b2    = (const float*)d_in[6];
    const float* pc1W  = (const float*)d_in[7];
    const float* pc1b  = (const float*)d_in[8];
    const float* w3    = (const float*)d_in[9];
    const float* b3    = (const float*)d_in[10];
    const float* w4    = (const float*)d_in[11];
    const float* b4    = (const float*)d_in[12];
    const float* pc2W  = (const float*)d_in[13];
    const float* pc2b  = (const float*)d_in[14];
    const float* w5    = (const float*)d_in[15];
    const float* b5    = (const float*)d_in[16];
    const float* w6    = (const float*)d_in[17];
    const float* b6    = (const float*)d_in[18];
    const int* far1    = (const int*)d_in[20];
    const int* far2    = (const int*)d_in[21];
    float* out = (float*)d_out;

    float *bufA, *bufB, *w3p, *w5p;
    cudaGetSymbolAddress((void**)&bufA, g_bufA);
    cudaGetSymbolAddress((void**)&bufB, g_bufB);
    cudaGetSymbolAddress((void**)&w3p,  g_w3p);
    cudaGetSymbolAddress((void**)&w5p,  g_w5p);

    cudaFuncSetAttribute(gemm_hmma, cudaFuncAttributeMaxDynamicSharedMemorySize, GEMM_SMEM);

    pack_weights<<<(256 * 264 + 384 * 392 + 255) / 256, 256>>>(w3, w5);
    point_mlp1<<<(NROWS * 16 + 255) / 256, 256>>>(x, confW, confb, w1, b1);
    fps_kernel<<<256, 32>>>(x, far1, far2);

    // l2 = relu(l1 @ w2^T + b2)   : bufA -> bufB  (64000x256, K=64)
    gemm_hmma<<<dim3(1, 500), 256, GEMM_SMEM>>>(bufA, w2, b2, bufB, NROWS, 256, 64, 1);
    // l3 = l2 @ pc1^T + pc1b      : bufB -> bufA  (64000x256, K=256)
    gemm_hmma<<<dim3(1, 500), 256, GEMM_SMEM>>>(bufB, pc1W, pc1b, bufA, NROWS, 256, 256, 0);
    gather1_kernel<<<(NROWS * 66 + 255) / 256, 256>>>(x);
    // l4 = relu(nf1 @ w3^T + b3)  : bufB -> bufA  (64000x256, K=264)
    gemm_hmma<<<dim3(1, 500), 256, GEMM_SMEM>>>(bufB, w3p, b3, bufA, NROWS, 256, 264, 1);
    // l5 = relu(l4 @ w4^T + b4)   : bufA -> bufB  (64000x384, K=256)
    gemm_hmma<<<dim3(2, 500), 256, GEMM_SMEM>>>(bufA, w4, b4, bufB, NROWS, 384, 256, 1);
    // l6 = l5 @ pc2^T + pc2b      : bufB -> bufA  (64000x384, K=384)
    gemm_hmma<<<dim3(2, 500), 256, GEMM_SMEM>>>(bufB, pc2W, pc2b, bufA, NROWS, 384, 384, 0);
    gather2_kernel<<<(128000 * 98 + 255) / 256, 256>>>(x);
    // l7 = relu(nf2 @ w5^T + b5)  : bufB -> bufA  (128000x384, K=392)
    gemm_hmma<<<dim3(2, 1000), 256, GEMM_SMEM>>>(bufB, w5p, b5, bufA, 128000, 384, 392, 1);
    // l8 = relu(l7 @ w6^T + b6)   : bufA -> bufB  (128000x512, K=384)
    gemm_hmma<<<dim3(2, 1000), 256, GEMM_SMEM>>>(bufA, w6, b6, bufB, 128000, 512, 384, 1);

    maxpool_kernel<<<(BATCH * 512 + 255) / 256, 256>>>(bufB, out);
}

// round 4
// speedup vs baseline: 2.5534x; 2.5534x over previous
#include <cuda_runtime.h>
#include <cuda_bf16.h>
#include <math.h>
#include <cstdint>

#define BATCH 128
#define NPT   500
#define NROWS (BATCH*NPT)

typedef unsigned long long ull;

// ---------------- scratch (static; no allocation) ----------------
__device__ __align__(256) __nv_bfloat16 g_hiP[65536000];
__device__ __align__(256) __nv_bfloat16 g_loP[65536000];
__device__ __align__(256) __nv_bfloat16 g_hiQ[65536000];
__device__ __align__(256) __nv_bfloat16 g_loQ[65536000];
__device__ __align__(256) float g_f32[65536000];
__device__ __align__(256) __nv_bfloat16 g_wHi[742528];
__device__ __align__(256) __nv_bfloat16 g_wLo[742528];
__device__ __align__(256) int g_idx1[BATCH * 500];
__device__ __align__(256) int g_idx2[BATCH * 1000];

// weight arena offsets (elements)
#define OFF_W2   0
#define OFF_PC1  16384
#define OFF_W3   81920
#define OFF_W4   149504
#define OFF_PC2  247808
#define OFF_W5   395264
#define OFF_W6   545792

// ---------------- helpers ----------------
__device__ __forceinline__ uint32_t smem_u32(const void* p) {
    uint32_t a;
    asm("{ .reg .u64 t; cvta.to.shared.u64 t, %1; cvt.u32.u64 %0, t; }" : "=r"(a) : "l"(p));
    return a;
}
__device__ __forceinline__ void cpa16(uint32_t dst, const void* src, int sz) {
    asm volatile("cp.async.cg.shared.global [%0], [%1], 16, %2;"
        :: "r"(dst), "l"(src), "r"(sz) : "memory");
}
__device__ __forceinline__ void ldm_x4(uint32_t* r, uint32_t addr) {
    asm volatile("ldmatrix.sync.aligned.m8n8.x4.shared.b16 {%0,%1,%2,%3}, [%4];"
        : "=r"(r[0]), "=r"(r[1]), "=r"(r[2]), "=r"(r[3]) : "r"(addr));
}
__device__ __forceinline__ void ldm_x2(uint32_t& r0, uint32_t& r1, uint32_t addr) {
    asm volatile("ldmatrix.sync.aligned.m8n8.x2.shared.b16 {%0,%1}, [%2];"
        : "=r"(r0), "=r"(r1) : "r"(addr));
}
__device__ __forceinline__ void mma_bf16(float* d, const uint32_t* a, uint32_t b0, uint32_t b1) {
    asm volatile("mma.sync.aligned.m16n8k16.row.col.f32.bf16.bf16.f32 "
        "{%0,%1,%2,%3}, {%4,%5,%6,%7}, {%8,%9}, {%0,%1,%2,%3};"
        : "+f"(d[0]), "+f"(d[1]), "+f"(d[2]), "+f"(d[3])
        : "r"(a[0]), "r"(a[1]), "r"(a[2]), "r"(a[3]), "r"(b0), "r"(b1));
}
// split a pair of fp32 into packed bf16 hi word + bf16 lo (residual) word
__device__ __forceinline__ void split2(float v0, float v1, uint32_t& h, uint32_t& l) {
    asm("cvt.rn.bf16x2.f32 %0, %1, %2;" : "=r"(h) : "f"(v1), "f"(v0));
    float r0 = v0 - __uint_as_float(h << 16);
    float r1 = v1 - __uint_as_float(h & 0xFFFF0000u);
    asm("cvt.rn.bf16x2.f32 %0, %1, %2;" : "=r"(l) : "f"(r1), "f"(r0));
}

// ---------------- bf16 split-input HMMA GEMM ----------------
// C = relu?( sum_k A[m,k]*W[n,k] + bias[n] ), A/W given as bf16 (hi,lo) pairs.
// D = Ah*Wh + Al*Wh + Ah*Wl (fp32 accum). CTA 128x128, 8 warps (2Mx4N), warp 64x32.
// 3-stage cp.async pipeline, 64KB/stage: Ah|Al|Wh|Wl 16KB each, SW128 swizzle.
#define NSTG 3
#define STG 65536
static const int GEMM_SMEM = NSTG * STG;

__device__ __forceinline__ void g_fill(
    const __nv_bfloat16* __restrict__ Ah, const __nv_bfloat16* __restrict__ Al,
    const __nv_bfloat16* __restrict__ Wh, const __nv_bfloat16* __restrict__ Wl,
    int K, int row0, int col0, int s, int nst, uint32_t sb, int tid)
{
    if (s < nst) {
        int k0 = s << 6;
        uint32_t base = sb + (uint32_t)(s % NSTG) * STG;
#pragma unroll
        for (int i = 0; i < 4; i++) {
            int g = (i << 8) + tid;
            int r = g >> 3, c = g & 7;
            int kg = k0 + (c << 3);
            int ok = (kg < K) ? 16 : 0;
            uint32_t d = base + ((uint32_t)r << 7) + (((uint32_t)(c ^ (r & 7))) << 4);
            size_t ao = (size_t)(row0 + r) * K + kg;
            size_t bo = (size_t)(col0 + r) * K + kg;
            cpa16(d,         Ah + ao, ok);
            cpa16(d + 16384, Al + ao, ok);
            cpa16(d + 32768, Wh + bo, ok);
            cpa16(d + 49152, Wl + bo, ok);
        }
    }
    asm volatile("cp.async.commit_group;" ::: "memory");
}

__global__ void __launch_bounds__(256, 1)
gemm_bf16(const __nv_bfloat16* __restrict__ Ah, const __nv_bfloat16* __restrict__ Al,
          const __nv_bfloat16* __restrict__ Wh, const __nv_bfloat16* __restrict__ Wl,
          const float* __restrict__ bias,
          float* __restrict__ Cf,
          __nv_bfloat16* __restrict__ Chi, __nv_bfloat16* __restrict__ Clo,
          int M, int N, int K, int relu, int mode)
{
    extern __shared__ char smem[];
    uint32_t sb = smem_u32(smem);
    int tid = threadIdx.x, lane = tid & 31, wid = tid >> 5;
    int warp_m = wid & 1;        // 64 rows each
    int warp_n = wid >> 1;       // 32 cols each
    int row0 = blockIdx.y << 7;
    int col0 = blockIdx.x << 7;
    int nst = (K + 63) >> 6;

    float acc[4][4][4];
#pragma unroll
    for (int a = 0; a < 4; a++)
#pragma unroll
        for (int b = 0; b < 4; b++)
#pragma unroll
            for (int c = 0; c < 4; c++) acc[a][b][c] = 0.f;

    g_fill(Ah, Al, Wh, Wl, K, row0, col0, 0, nst, sb, tid);
    g_fill(Ah, Al, Wh, Wl, K, row0, col0, 1, nst, sb, tid);

    int a_row = warp_m * 64 + (lane & 15);
    int a_sel = lane >> 4;
    int b_row = warp_n * 32 + (lane & 7);
    int b_sel = (lane >> 3) & 1;

    for (int s = 0; s < nst; s++) {
        asm volatile("cp.async.wait_group 1;" ::: "memory");
        __syncthreads();
        uint32_t base = sb + (uint32_t)(s % NSTG) * STG;
        int kr = K - (s << 6);
        int kcnt = (kr + 15) >> 4; if (kcnt > 4) kcnt = 4;
        for (int ks = 0; ks < kcnt; ks++) {
            uint32_t Afh[4][4], Afl[4][4];
#pragma unroll
            for (int mi = 0; mi < 4; mi++) {
                int rr = a_row + mi * 16;
                int ch = (ks << 1) + a_sel;
                uint32_t sw = base + ((uint32_t)rr << 7) + (((uint32_t)(ch ^ (rr & 7))) << 4);
                ldm_x4(Afh[mi], sw);
                ldm_x4(Afl[mi], sw + 16384);
            }
#pragma unroll
            for (int ni = 0; ni < 4; ni++) {
                int nr = b_row + ni * 8;
                int ch = (ks << 1) + b_sel;
                uint32_t sw = base + ((uint32_t)nr << 7) + (((uint32_t)(ch ^ (nr & 7))) << 4);
                uint32_t bh0, bh1, bl0, bl1;
                ldm_x2(bh0, bh1, sw + 32768);
                ldm_x2(bl0, bl1, sw + 49152);
#pragma unroll
                for (int mi = 0; mi < 4; mi++) {
                    mma_bf16(acc[mi][ni], Afh[mi], bh0, bh1);
                    mma_bf16(acc[mi][ni], Afl[mi], bh0, bh1);
                    mma_bf16(acc[mi][ni], Afh[mi], bl0, bl1);
                }
            }
        }
        // buffer (s+2)%3 was consumed in stage s-1; all warps passed the top barrier
        g_fill(Ah, Al, Wh, Wl, K, row0, col0, s + 2, nst, sb, tid);
    }

    // epilogue
    int er = row0 + warp_m * 64 + (lane >> 2);
    int ec = col0 + warp_n * 32 + ((lane & 3) << 1);
#pragma unroll
    for (int ni = 0; ni < 4; ni++) {
        int c = ec + ni * 8;
        float b0 = __ldg(bias + c), b1 = __ldg(bias + c + 1);
#pragma unroll
        for (int mi = 0; mi < 4; mi++) {
            int r = er + mi * 16;
            float v00 = acc[mi][ni][0] + b0, v01 = acc[mi][ni][1] + b1;
            float v10 = acc[mi][ni][2] + b0, v11 = acc[mi][ni][3] + b1;
            if (relu) {
                v00 = fmaxf(v00, 0.f); v01 = fmaxf(v01, 0.f);
                v10 = fmaxf(v10, 0.f); v11 = fmaxf(v11, 0.f);
            }
            if (mode == 0) {
                *(float2*)(Cf + (size_t)r * N + c)       = make_float2(v00, v01);
                *(float2*)(Cf + (size_t)(r + 8) * N + c) = make_float2(v10, v11);
            } else {
                uint32_t h, l;
                split2(v00, v01, h, l);
                *(uint32_t*)(Chi + (size_t)r * N + c) = h;
                *(uint32_t*)(Clo + (size_t)r * N + c) = l;
                split2(v10, v11, h, l);
                *(uint32_t*)(Chi + (size_t)(r + 8) * N + c) = h;
                *(uint32_t*)(Clo + (size_t)(r + 8) * N + c) = l;
            }
        }
    }
}

// ---------------- weight split/pad (fp32 -> bf16 hi/lo arena) ----------------
__global__ void pack_w(const float* __restrict__ w2, const float* __restrict__ pc1,
                       const float* __restrict__ w3, const float* __restrict__ w4,
                       const float* __restrict__ pc2, const float* __restrict__ w5,
                       const float* __restrict__ w6) {
    int t = blockIdx.x * 256 + threadIdx.x;
    if (t >= 742400) return;
    float v;
    if (t < 81920) {
        v = (t < 16384) ? w2[t] : pc1[t - 16384];
    } else if (t < 149504) {
        int i = t - 81920; int r = i / 264, c = i - r * 264;
        v = (c < 259) ? w3[r * 259 + c] : 0.f;
    } else if (t < 247808) {
        v = w4[t - 149504];
    } else if (t < 395264) {
        v = pc2[t - 247808];
    } else if (t < 545792) {
        int i = t - 395264; int r = i / 392, c = i - r * 392;
        v = (c < 387) ? w5[r * 387 + c] : 0.f;
    } else {
        v = w6[t - 545792];
    }
    __nv_bfloat16 h = __float2bfloat16(v);
    g_wHi[t] = h;
    g_wLo[t] = __float2bfloat16(v - __bfloat162float(h));
}

// ---------------- fused conf + concat + first linear -> bf16 hi/lo ----------------
__global__ void point_mlp1(const float* __restrict__ x,
                           const float* __restrict__ confW, const float* __restrict__ confb,
                           const float* __restrict__ w1, const float* __restrict__ b1) {
    int t = blockIdx.x * 256 + threadIdx.x;
    if (t >= NROWS * 16) return;
    int p = t >> 4, g = t & 15;
    float x0 = x[p * 3], x1 = x[p * 3 + 1], x2 = x[p * 3 + 2];
    float s = confW[0] * x0 + confW[1] * x1 + confW[2] * x2 + confb[0];
    float conf = 1.f / (1.f + expf(-s));
    const float* wr = w1 + (g * 4) * 4;
    float v[4];
#pragma unroll
    for (int r = 0; r < 4; r++) {
        float a = b1[g * 4 + r]
                + wr[r * 4 + 0] * conf + wr[r * 4 + 1] * x0
                + wr[r * 4 + 2] * x1   + wr[r * 4 + 3] * x2;
        v[r] = fmaxf(a, 0.f);
    }
    uint32_t h0, l0, h1, l1;
    split2(v[0], v[1], h0, l0);
    split2(v[2], v[3], h1, l1);
    size_t o = (size_t)p * 64 + g * 4;
    *(uint2*)(g_hiP + o) = make_uint2(h0, h1);
    *(uint2*)(g_loP + o) = make_uint2(l0, l1);
}

// ---------------- farthest point sampling (bitwise-matches XLA) ----------------
__global__ void fps_kernel(const float* __restrict__ x,
                           const int* __restrict__ far1, const int* __restrict__ far2) {
    __shared__ float sxx[512], sxy[512], sxz[512];
    int which = blockIdx.x >> 7;
    int b = blockIdx.x & 127;
    int npoint = which ? 1000 : 500;
    int* out = (which ? g_idx2 : g_idx1) + b * npoint;
    int far = which ? far2[b] : far1[b];
    const float* xb = x + (size_t)b * NPT * 3;
    int lane = threadIdx.x;

    float px[16], py[16], pz[16], dist[16];
#pragma unroll
    for (int j = 0; j < 16; j++) {
        int p = j * 32 + lane;
        if (p < NPT) {
            px[j] = xb[p * 3]; py[j] = xb[p * 3 + 1]; pz[j] = xb[p * 3 + 2];
            dist[j] = 1e10f;
            sxx[p] = px[j]; sxy[p] = py[j]; sxz[p] = pz[j];
        } else {
            px[j] = 0.f; py[j] = 0.f; pz[j] = 0.f;
            dist[j] = -1.0f;
        }
    }
    __syncwarp();

    for (int t = 0; t < npoint; t++) {
        if (lane == 0) out[t] = far;
        if (t + 1 == npoint) break;
        float cx = sxx[far], cy = sxy[far], cz = sxz[far];
        float nd[16];
#pragma unroll
        for (int j = 0; j < 16; j++) {
            float dx = __fsub_rn(px[j], cx);
            float dy = __fsub_rn(py[j], cy);
            float dz = __fsub_rn(pz[j], cz);
            float d  = __fadd_rn(__fadd_rn(__fmul_rn(dx, dx), __fmul_rn(dy, dy)),
                                 __fmul_rn(dz, dz));
            nd[j] = fminf(dist[j], d);
            dist[j] = nd[j];
        }
        float m[8];
#pragma unroll
        for (int j = 0; j < 8; j++) m[j] = fmaxf(nd[2 * j], nd[2 * j + 1]);
#pragma unroll
        for (int j = 0; j < 4; j++) m[j] = fmaxf(m[j], m[j + 4]);
        m[0] = fmaxf(m[0], m[2]); m[1] = fmaxf(m[1], m[3]);
        float best = fmaxf(m[0], m[1]);
        unsigned mb = __reduce_max_sync(0xffffffffu, __float_as_uint(best));
        unsigned c[16];
#pragma unroll
        for (int j = 0; j < 16; j++)
            c[j] = (__float_as_uint(nd[j]) == mb) ? (unsigned)(j * 32 + lane) : 0xffffffffu;
#pragma unroll
        for (int j = 0; j < 8; j++) c[j] = min(c[j], c[j + 8]);
#pragma unroll
        for (int j = 0; j < 4; j++) c[j] = min(c[j], c[j + 4]);
        c[0] = min(c[0], c[2]); c[1] = min(c[1], c[3]);
        far = (int)__reduce_min_sync(0xffffffffu, min(c[0], c[1]));
    }
}

// ---------------- gathers (bf16 hi/lo, 16B chunks; pad K with zeros) ----------------
__global__ void gather1b(const float* __restrict__ x) {
    int t = blockIdx.x * 256 + threadIdx.x;
    if (t >= NROWS * 33) return;
    int r = t / 33, c = t - r * 33;
    int b = r / 500;
    int i = g_idx1[r];
    size_t src = (size_t)b * 500 + i;
    size_t drow = (size_t)r * 264;
    if (c < 32) {
        *(uint4*)(g_hiQ + drow + c * 8) = *(const uint4*)(g_hiP + src * 256 + c * 8);
        *(uint4*)(g_loQ + drow + c * 8) = *(const uint4*)(g_loP + src * 256 + c * 8);
    } else {
        const float* xp = x + src * 3;
        __nv_bfloat16 h[8], l[8];
#pragma unroll
        for (int j = 0; j < 8; j++) { h[j] = __float2bfloat16(0.f); l[j] = h[j]; }
#pragma unroll
        for (int j = 0; j < 3; j++) {
            float v = xp[j];
            h[j] = __float2bfloat16(v);
            l[j] = __float2bfloat16(v - __bfloat162float(h[j]));
        }
        *(uint4*)(g_hiQ + drow + 256) = *(uint4*)h;
        *(uint4*)(g_loQ + drow + 256) = *(uint4*)l;
    }
}
__global__ void gather2b(const float* __restrict__ x) {
    int t = blockIdx.x * 256 + threadIdx.x;
    if (t >= 128000 * 49) return;
    int r = t / 49, c = t - r * 49;
    int b = r / 1000;
    int i = g_idx2[r];
    size_t src = (size_t)b * 500 + i;
    size_t drow = (size_t)r * 392;
    if (c < 48) {
        *(uint4*)(g_hiQ + drow + c * 8) = *(const uint4*)(g_hiP + src * 384 + c * 8);
        *(uint4*)(g_loQ + drow + c * 8) = *(const uint4*)(g_loP + src * 384 + c * 8);
    } else {
        const float* xp = x + src * 3;
        __nv_bfloat16 h[8], l[8];
#pragma unroll
        for (int j = 0; j < 8; j++) { h[j] = __float2bfloat16(0.f); l[j] = h[j]; }
#pragma unroll
        for (int j = 0; j < 3; j++) {
            float v = xp[j];
            h[j] = __float2bfloat16(v);
            l[j] = __float2bfloat16(v - __bfloat162float(h[j]));
        }
        *(uint4*)(g_hiQ + drow + 384) = *(uint4*)h;
        *(uint4*)(g_loQ + drow + 384) = *(uint4*)l;
    }
}

// ---------------- max-pool ----------------
__global__ void maxpool_kernel(const float* __restrict__ l8, float* __restrict__ out) {
    int t = blockIdx.x * 256 + threadIdx.x;
    if (t >= BATCH * 512) return;
    int b = t >> 9, c = t & 511;
    const float* p = l8 + (size_t)b * 1000 * 512 + c;
    float m = -1e30f;
#pragma unroll 4
    for (int i = 0; i < 1000; i++) m = fmaxf(m, p[(size_t)i * 512]);
    out[t] = m;
}

// ---------------- launch ----------------
extern "C" void kernel_launch(void* const* d_in, const int* in_sizes, int n_in,
                              void* d_out, int out_size) {
    const float* x     = (const float*)d_in[0];
    const float* confW = (const float*)d_in[1];
    const float* confb = (const float*)d_in[2];
    const float* w1    = (const float*)d_in[3];
    const float* b1    = (const float*)d_in[4];
    const float* w2    = (const float*)d_in[5];
    const float* b2    = (const float*)d_in[6];
    const float* pc1W  = (const float*)d_in[7];
    const float* pc1b  = (const float*)d_in[8];
    const float* w3    = (const float*)d_in[9];
    const float* b3    = (const float*)d_in[10];
    const float* w4    = (const float*)d_in[11];
    const float* b4    = (const float*)d_in[12];
    const float* pc2W  = (const float*)d_in[13];
    const float* pc2b  = (const float*)d_in[14];
    const float* w5    = (const float*)d_in[15];
    const float* b5    = (const float*)d_in[16];
    const float* w6    = (const float*)d_in[17];
    const float* b6    = (const float*)d_in[18];
    const int* far1    = (const int*)d_in[20];
    const int* far2    = (const int*)d_in[21];
    float* out = (float*)d_out;

    __nv_bfloat16 *hiP, *loP, *hiQ, *loQ, *wHi, *wLo;
    float* f32;
    cudaGetSymbolAddress((void**)&hiP, g_hiP);
    cudaGetSymbolAddress((void**)&loP, g_loP);
    cudaGetSymbolAddress((void**)&hiQ, g_hiQ);
    cudaGetSymbolAddress((void**)&loQ, g_loQ);
    cudaGetSymbolAddress((void**)&wHi, g_wHi);
    cudaGetSymbolAddress((void**)&wLo, g_wLo);
    cudaGetSymbolAddress((void**)&f32, g_f32);

    cudaFuncSetAttribute(gemm_bf16, cudaFuncAttributeMaxDynamicSharedMemorySize, GEMM_SMEM);

    pack_w<<<(742400 + 255) / 256, 256>>>(w2, pc1W, w3, w4, pc2W, w5, w6);
    point_mlp1<<<(NROWS * 16 + 255) / 256, 256>>>(x, confW, confb, w1, b1);
    fps_kernel<<<256, 32>>>(x, far1, far2);

    // l2: (64000x256, K=64), relu
    gemm_bf16<<<dim3(2, 500), 256, GEMM_SMEM>>>(hiP, loP, wHi + OFF_W2, wLo + OFF_W2,
        b2, nullptr, hiQ, loQ, NROWS, 256, 64, 1, 1);
    // l3: (64000x256, K=256)
    gemm_bf16<<<dim3(2, 500), 256, GEMM_SMEM>>>(hiQ, loQ, wHi + OFF_PC1, wLo + OFF_PC1,
        pc1b, nullptr, hiP, loP, NROWS, 256, 256, 0, 1);
    gather1b<<<(NROWS * 33 + 255) / 256, 256>>>(x);
    // l4: (64000x256, K=264), relu
    gemm_bf16<<<dim3(2, 500), 256, GEMM_SMEM>>>(hiQ, loQ, wHi + OFF_W3, wLo + OFF_W3,
        b3, nullptr, hiP, loP, NROWS, 256, 264, 1, 1);
    // l5: (64000x384, K=256), relu
    gemm_bf16<<<dim3(3, 500), 256, GEMM_SMEM>>>(hiP, loP, wHi + OFF_W4, wLo + OFF_W4,
        b4, nullptr, hiQ, loQ, NROWS, 384, 256, 1, 1);
    // l6: (64000x384, K=384)
    gemm_bf16<<<dim3(3, 500), 256, GEMM_SMEM>>>(hiQ, loQ, wHi + OFF_PC2, wLo + OFF_PC2,
        pc2b, nullptr, hiP, loP, NROWS, 384, 384, 0, 1);
    gather2b<<<(128000 * 49 + 255) / 256, 256>>>(x);
    // l7: (128000x384, K=392), relu
    gemm_bf16<<<dim3(3, 1000), 256, GEMM_SMEM>>>(hiQ, loQ, wHi + OFF_W5, wLo + OFF_W5,
        b5, nullptr, hiP, loP, 128000, 384, 392, 1, 1);
    // l8: (128000x512, K=384), relu, fp32 out
    gemm_bf16<<<dim3(4, 1000), 256, GEMM_SMEM>>>(hiP, loP, wHi + OFF_W6, wLo + OFF_W6,
        b6, f32, nullptr, nullptr, 128000, 512, 384, 1, 0);

    maxpool_kernel<<<(BATCH * 512 + 255) / 256, 256>>>(f32, out);
}